// round 1
// baseline (speedup 1.0000x reference)
#include <cuda_runtime.h>
#include <math.h>

// Problem constants
#define BB 16
#define TT 512
#define CC 256
#define HH 8
#define HS_T 32
#define HS_S 64
#define ROWS_T (BB*TT)      // 8192
#define ROWS_S (BB*CC)      // 4096

// ---------------- scratch (device globals; no allocation allowed) ----------------
__device__ float g_h[ROWS_T*CC];        // LN outputs (reused for h, h2, h3)
__device__ float g_qkv[ROWS_T*3*CC];    // [B,T, 3*256] q|k|v
__device__ float g_o[ROWS_T*CC];        // attention output (concat heads)
__device__ float g_x[ROWS_T*CC];        // x after attn residual
__device__ float g_u[ROWS_T*4*CC];      // FFN hidden (reused)
__device__ float g_to[ROWS_T*CC];       // temporal_out
__device__ float g_hs[ROWS_S*TT];       // spatial LN output [B,C,T]
__device__ float g_qks[ROWS_S*2*512];   // [B*C, 1024] qs|ks
__device__ float g_sc[BB*HH*CC*CC];     // spatial scores
__device__ float g_x2[ROWS_T*CC];       // temporal_out + fused

// ---------------- generic tiled SGEMM:  C = A @ B^T (+bias,+res,relu) ----------------
// A[m*lda+k], B[n*ldb+k], C[m*ldc+n].  2-level batch via blockIdx.z -> (b1,b2).
#define BM 64
#define BN 64
#define BKK 16

__global__ void gemm_kernel(const float* __restrict__ A, const float* __restrict__ Bw,
                            const float* __restrict__ bias, const float* __restrict__ res,
                            float* __restrict__ C,
                            int M, int N, int K, int lda, int ldb, int ldc,
                            int nb2,
                            long long sA1, long long sA2, long long sB1, long long sB2,
                            long long sC1, long long sC2, int relu)
{
    int z = blockIdx.z;
    int b1 = z / nb2, b2 = z - b1 * nb2;
    A  += (long long)b1 * sA1 + (long long)b2 * sA2;
    Bw += (long long)b1 * sB1 + (long long)b2 * sB2;
    long long co = (long long)b1 * sC1 + (long long)b2 * sC2;
    C += co;
    if (res) res += co;

    __shared__ float As[BKK][BM + 1];
    __shared__ float Bs[BKK][BN + 1];

    int tid = threadIdx.x;
    int tx = tid & 15, ty = tid >> 4;
    int bm = blockIdx.y * BM, bn = blockIdx.x * BN;

    float acc[4][4];
#pragma unroll
    for (int i = 0; i < 4; i++)
#pragma unroll
        for (int j = 0; j < 4; j++) acc[i][j] = 0.f;

    for (int k0 = 0; k0 < K; k0 += BKK) {
#pragma unroll
        for (int i = 0; i < 4; i++) {
            int idx = tid + i * 256;
            int m = idx >> 4, k = idx & 15;
            int gm = bm + m, gk = k0 + k;
            As[k][m] = (gm < M) ? A[(long long)gm * lda + gk] : 0.f;
        }
#pragma unroll
        for (int i = 0; i < 4; i++) {
            int idx = tid + i * 256;
            int n = idx >> 4, k = idx & 15;
            int gn = bn + n, gk = k0 + k;
            Bs[k][n] = (gn < N) ? Bw[(long long)gn * ldb + gk] : 0.f;
        }
        __syncthreads();
#pragma unroll
        for (int kk = 0; kk < BKK; kk++) {
            float a[4], b[4];
#pragma unroll
            for (int i = 0; i < 4; i++) a[i] = As[kk][ty * 4 + i];
#pragma unroll
            for (int j = 0; j < 4; j++) b[j] = Bs[kk][tx * 4 + j];
#pragma unroll
            for (int i = 0; i < 4; i++)
#pragma unroll
                for (int j = 0; j < 4; j++) acc[i][j] += a[i] * b[j];
        }
        __syncthreads();
    }

#pragma unroll
    for (int i = 0; i < 4; i++) {
        int gm = bm + ty * 4 + i;
        if (gm >= M) continue;
#pragma unroll
        for (int j = 0; j < 4; j++) {
            int gn = bn + tx * 4 + j;
            if (gn >= N) continue;
            float v = acc[i][j];
            if (bias) v += bias[gn];
            if (res)  v += res[(long long)gm * ldc + gn];
            if (relu) v = fmaxf(v, 0.f);
            C[(long long)gm * ldc + gn] = v;
        }
    }
}

// ---------------- LayerNorm: one block per row ----------------
__global__ void ln_kernel(const float* __restrict__ x, const float* __restrict__ w,
                          const float* __restrict__ bp, float* __restrict__ y, int D)
{
    long long row = blockIdx.x;
    const float* xr = x + row * D;
    float* yr = y + row * D;
    __shared__ float red[256];
    int tid = threadIdx.x;
    int n = D >> 8;                 // 1 (D=256) or 2 (D=512)
    float vals[2];
    float s = 0.f, sq = 0.f;
    for (int i = 0; i < n; i++) {
        float t = xr[tid + i * 256];
        vals[i] = t; s += t; sq += t * t;
    }
    red[tid] = s; __syncthreads();
    for (int off = 128; off; off >>= 1) { if (tid < off) red[tid] += red[tid + off]; __syncthreads(); }
    float mean = red[0] / D; __syncthreads();
    red[tid] = sq; __syncthreads();
    for (int off = 128; off; off >>= 1) { if (tid < off) red[tid] += red[tid + off]; __syncthreads(); }
    float var = red[0] / D - mean * mean;
    float inv = rsqrtf(var + 1e-6f);
    for (int i = 0; i < n; i++) {
        int c = tid + i * 256;
        yr[c] = (vals[i] - mean) * inv * w[c] + bp[c];
    }
}

// ---------------- causal flash attention (D=32), 64 q-rows per block ----------------
// qkv layout: [B,T,768]: q at col h*32+d, k at 256+h*32+d, v at 512+h*32+d
__global__ void attn_kernel(const float* __restrict__ qkv, float* __restrict__ O)
{
    int qb = blockIdx.x;            // 0..7
    int bh = blockIdx.y;            // 0..127
    int b = bh >> 3, hh = bh & 7;
    int tid = threadIdx.x;          // 256
    int tx = tid & 15, ty = tid >> 4;

    __shared__ float Qs[64][33], Ks[64][33], Vs[64][33];
    __shared__ float Ps[64][65];

    // load Q block
#pragma unroll
    for (int i = 0; i < 8; i++) {
        int idx = tid + i * 256;
        int r = idx >> 5, d = idx & 31;
        Qs[r][d] = qkv[((long long)(b * TT + qb * 64 + r) * 768) + hh * 32 + d];
    }

    float m_i[4], l_i[4], oacc[4][2];
#pragma unroll
    for (int i = 0; i < 4; i++) { m_i[i] = -1e30f; l_i[i] = 0.f; oacc[i][0] = 0.f; oacc[i][1] = 0.f; }

    const float scale = 0.17677669529663687f; // 1/sqrt(32)

    for (int kb = 0; kb <= qb; kb++) {
        __syncthreads();
#pragma unroll
        for (int i = 0; i < 8; i++) {
            int idx = tid + i * 256;
            int r = idx >> 5, d = idx & 31;
            long long base = (long long)(b * TT + kb * 64 + r) * 768 + hh * 32 + d;
            Ks[r][d] = qkv[base + 256];
            Vs[r][d] = qkv[base + 512];
        }
        __syncthreads();

        float s[4][4];
#pragma unroll
        for (int i = 0; i < 4; i++)
#pragma unroll
            for (int j = 0; j < 4; j++) s[i][j] = 0.f;
#pragma unroll
        for (int d = 0; d < 32; d++) {
            float a[4], bb[4];
#pragma unroll
            for (int i = 0; i < 4; i++) a[i] = Qs[ty * 4 + i][d];
#pragma unroll
            for (int j = 0; j < 4; j++) bb[j] = Ks[tx * 4 + j][d];
#pragma unroll
            for (int i = 0; i < 4; i++)
#pragma unroll
                for (int j = 0; j < 4; j++) s[i][j] += a[i] * bb[j];
        }
        if (kb == qb) {
#pragma unroll
            for (int i = 0; i < 4; i++)
#pragma unroll
                for (int j = 0; j < 4; j++)
                    s[i][j] = (tx * 4 + j > ty * 4 + i) ? -1e30f : s[i][j] * scale;
        } else {
#pragma unroll
            for (int i = 0; i < 4; i++)
#pragma unroll
                for (int j = 0; j < 4; j++) s[i][j] *= scale;
        }

#pragma unroll
        for (int i = 0; i < 4; i++) {
            float rmax = fmaxf(fmaxf(s[i][0], s[i][1]), fmaxf(s[i][2], s[i][3]));
#pragma unroll
            for (int off = 8; off; off >>= 1)
                rmax = fmaxf(rmax, __shfl_xor_sync(0xffffffffu, rmax, off));
            float newm = fmaxf(m_i[i], rmax);
            float alpha = __expf(m_i[i] - newm);
            float rsum = 0.f;
#pragma unroll
            for (int j = 0; j < 4; j++) {
                float p = __expf(s[i][j] - newm);
                s[i][j] = p; rsum += p;
            }
#pragma unroll
            for (int off = 8; off; off >>= 1)
                rsum += __shfl_xor_sync(0xffffffffu, rsum, off);
            l_i[i] = l_i[i] * alpha + rsum;
            m_i[i] = newm;
            oacc[i][0] *= alpha; oacc[i][1] *= alpha;
#pragma unroll
            for (int j = 0; j < 4; j++) Ps[ty * 4 + i][tx * 4 + j] = s[i][j];
        }
        __syncthreads();
        // O += P @ V
#pragma unroll
        for (int ss = 0; ss < 64; ss++) {
            float v0 = Vs[ss][tx * 2], v1 = Vs[ss][tx * 2 + 1];
#pragma unroll
            for (int i = 0; i < 4; i++) {
                float p = Ps[ty * 4 + i][ss];
                oacc[i][0] += p * v0;
                oacc[i][1] += p * v1;
            }
        }
    }

#pragma unroll
    for (int i = 0; i < 4; i++) {
        int t = qb * 64 + ty * 4 + i;
        float invl = 1.f / l_i[i];
        O[((long long)(b * TT + t) * CC) + hh * 32 + tx * 2 + 0] = oacc[i][0] * invl;
        O[((long long)(b * TT + t) * CC) + hh * 32 + tx * 2 + 1] = oacc[i][1] * invl;
    }
}

// ---------------- spatial softmax over e + mean over heads ----------------
// sc [B,H,C,C] -> sw [B,C,C];  sw[b,c,e] = mean_h softmax_e(sc[b,h,c,:]/8)
__global__ void smax_mean_kernel(const float* __restrict__ sc, float* __restrict__ sw)
{
    int bc = blockIdx.x;            // 0..4095
    int b = bc >> 8, c = bc & 255;
    int e = threadIdx.x;            // 256
    __shared__ float red[256];
    float acc = 0.f;
    for (int h = 0; h < 8; h++) {
        float v = sc[(((long long)(b * 8 + h) * CC + c) * CC) + e] * 0.125f;
        red[e] = v; __syncthreads();
        for (int off = 128; off; off >>= 1) { if (e < off) red[e] = fmaxf(red[e], red[e + off]); __syncthreads(); }
        float mx = red[0]; __syncthreads();
        float ev = __expf(v - mx);
        red[e] = ev; __syncthreads();
        for (int off = 128; off; off >>= 1) { if (e < off) red[e] += red[e + off]; __syncthreads(); }
        float sm = red[0]; __syncthreads();
        acc += ev / sm;
    }
    sw[(long long)bc * CC + e] = acc * 0.125f;
}

// ---------------- host launch ----------------
static void gemm(const float* A, const float* Bw, const float* bias, const float* res, float* C,
                 int M, int N, int K, int lda, int ldb, int ldc,
                 int nbatch, int nb2,
                 long long sA1, long long sA2, long long sB1, long long sB2,
                 long long sC1, long long sC2, int relu)
{
    dim3 grid((N + BN - 1) / BN, (M + BM - 1) / BM, nbatch);
    gemm_kernel<<<grid, 256>>>(A, Bw, bias, res, C, M, N, K, lda, ldb, ldc,
                               nb2, sA1, sA2, sB1, sB2, sC1, sC2, relu);
}

extern "C" void kernel_launch(void* const* d_in, const int* in_sizes, int n_in,
                              void* d_out, int out_size)
{
    const float* x_T     = (const float*)d_in[0];
    const float* x_S     = (const float*)d_in[1];
    const float* Wq_t    = (const float*)d_in[2];
    const float* Wk_t    = (const float*)d_in[3];
    const float* Wv_t    = (const float*)d_in[4];
    const float* Wo      = (const float*)d_in[5];
    const float* Wq_s    = (const float*)d_in[6];
    const float* Wk_s    = (const float*)d_in[7];
    const float* ff1_w1  = (const float*)d_in[8];
    const float* ff1_b1  = (const float*)d_in[9];
    const float* ff1_w2  = (const float*)d_in[10];
    const float* ff1_b2  = (const float*)d_in[11];
    const float* ff2_w1  = (const float*)d_in[12];
    const float* ff2_b1  = (const float*)d_in[13];
    const float* ff2_w2  = (const float*)d_in[14];
    const float* ff2_b2  = (const float*)d_in[15];
    const float* t_ln1_w = (const float*)d_in[16];
    const float* t_ln1_b = (const float*)d_in[17];
    const float* t_ln2_w = (const float*)d_in[18];
    const float* t_ln2_b = (const float*)d_in[19];
    const float* s_ln1_w = (const float*)d_in[20];
    const float* s_ln1_b = (const float*)d_in[21];
    const float* fus_ln_w= (const float*)d_in[22];
    const float* fus_ln_b= (const float*)d_in[23];

    float *h, *qkv, *o, *x, *u, *to, *hs, *qks, *sc, *x2;
    cudaGetSymbolAddress((void**)&h,   g_h);
    cudaGetSymbolAddress((void**)&qkv, g_qkv);
    cudaGetSymbolAddress((void**)&o,   g_o);
    cudaGetSymbolAddress((void**)&x,   g_x);
    cudaGetSymbolAddress((void**)&u,   g_u);
    cudaGetSymbolAddress((void**)&to,  g_to);
    cudaGetSymbolAddress((void**)&hs,  g_hs);
    cudaGetSymbolAddress((void**)&qks, g_qks);
    cudaGetSymbolAddress((void**)&sc,  g_sc);
    cudaGetSymbolAddress((void**)&x2,  g_x2);

    float* out = (float*)d_out;                 // [B,T,C] = 2097152 floats
    float* sw  = out + (long long)ROWS_T * CC;  // spatial_weights [B,C,C]

    // ---- temporal branch ----
    ln_kernel<<<ROWS_T, 256>>>(x_T, t_ln1_w, t_ln1_b, h, CC);
    gemm(h, Wq_t, 0, 0, qkv + 0,   ROWS_T, CC, CC, CC, CC, 3*CC, 1,1, 0,0,0,0,0,0, 0);
    gemm(h, Wk_t, 0, 0, qkv + CC,  ROWS_T, CC, CC, CC, CC, 3*CC, 1,1, 0,0,0,0,0,0, 0);
    gemm(h, Wv_t, 0, 0, qkv + 2*CC,ROWS_T, CC, CC, CC, CC, 3*CC, 1,1, 0,0,0,0,0,0, 0);
    attn_kernel<<<dim3(TT/64, BB*HH), 256>>>(qkv, o);
    gemm(o, Wo, 0, x_T, x, ROWS_T, CC, CC, CC, CC, CC, 1,1, 0,0,0,0,0,0, 0);
    ln_kernel<<<ROWS_T, 256>>>(x, t_ln2_w, t_ln2_b, h, CC);
    gemm(h, ff1_w1, ff1_b1, 0, u,  ROWS_T, 4*CC, CC, CC, CC, 4*CC, 1,1, 0,0,0,0,0,0, 1);
    gemm(u, ff1_w2, ff1_b2, x, to, ROWS_T, CC, 4*CC, 4*CC, 4*CC, CC, 1,1, 0,0,0,0,0,0, 0);

    // ---- spatial branch ----
    ln_kernel<<<ROWS_S, 256>>>(x_S, s_ln1_w, s_ln1_b, hs, TT);
    gemm(hs, Wq_s, 0, 0, qks + 0,   ROWS_S, 512, TT, TT, TT, 1024, 1,1, 0,0,0,0,0,0, 0);
    gemm(hs, Wk_s, 0, 0, qks + 512, ROWS_S, 512, TT, TT, TT, 1024, 1,1, 0,0,0,0,0,0, 0);
    // sc[b,h] = qs[b,h] @ ks[b,h]^T  (batched over b,h)
    gemm(qks, qks + 512, 0, 0, sc, CC, CC, HS_S, 1024, 1024, CC,
         BB*HH, HH,
         (long long)CC*1024, 64, (long long)CC*1024, 64,
         (long long)HH*CC*CC, (long long)CC*CC, 0);
    smax_mean_kernel<<<BB*CC, 256>>>(sc, sw);

    // ---- fusion: x2 = TO + TO @ sw^T  (batched over b) ----
    gemm(to, sw, 0, to, x2, TT, CC, CC, CC, CC, CC,
         BB, 1,
         (long long)TT*CC, 0, (long long)CC*CC, 0, (long long)TT*CC, 0, 0);

    // ---- FFN2 -> out ----
    ln_kernel<<<ROWS_T, 256>>>(x2, fus_ln_w, fus_ln_b, h, CC);
    gemm(h, ff2_w1, ff2_b1, 0, u, ROWS_T, 4*CC, CC, CC, CC, 4*CC, 1,1, 0,0,0,0,0,0, 1);
    gemm(u, ff2_w2, ff2_b2, x2, out, ROWS_T, CC, 4*CC, 4*CC, 4*CC, CC, 1,1, 0,0,0,0,0,0, 0);
}

// round 2
// speedup vs baseline: 2.7615x; 2.7615x over previous
#include <cuda_runtime.h>
#include <math.h>

// Problem constants
#define BB 16
#define TT 512
#define CC 256
#define HH 8
#define HS_T 32
#define HS_S 64
#define ROWS_T (BB*TT)      // 8192
#define ROWS_S (BB*CC)      // 4096

// ---------------- scratch (device globals; no allocation allowed) ----------------
__device__ float g_h[ROWS_T*CC];        // LN outputs (reused)
__device__ float g_qkv[ROWS_T*3*CC];    // [B,T, 3*256] q|k|v
__device__ float g_o[ROWS_T*CC];        // attention output
__device__ float g_x[ROWS_T*CC];        // x after attn residual
__device__ float g_u[ROWS_T*4*CC];      // FFN hidden
__device__ float g_to[ROWS_T*CC];       // temporal_out
__device__ float g_hs[ROWS_S*TT];       // spatial LN output [B,C,T]
__device__ float g_qks[ROWS_S*2*512];   // [B*C, 1024] qs|ks
__device__ float g_sc[BB*HH*CC*CC];     // spatial scores
__device__ float g_x2[ROWS_T*CC];       // temporal_out + fused
__device__ float g_wqkv[768*256];       // packed Wq_t|Wk_t|Wv_t
__device__ float g_wqks[1024*512];      // packed Wq_s|Wk_s

// ================= tf32 tensor-core GEMM:  C = A @ B^T (+bias,+res,relu) =========
// A[m*lda+k], B[n*ldb+k] (both row-major, K contiguous), C[m*ldc+n].
// REQUIRES: M%128==0, N%128==0, K%16==0, lda/ldb multiples of 4, 16B-aligned bases.
// 2-level batch via blockIdx.z -> (b1,b2).
#define BM 128
#define BN 128
#define BK 16
#define ASTR 20     // (20*r + c) % 32 distinct for r in 0..7, c in 0..3 -> conflict-free
#define BSTR 136    // 136 % 32 == 8 -> (8*k + n) distinct for k in 0..3, n in 0..7

__device__ __forceinline__ unsigned f2tf(float f) {
    unsigned u;
    asm("cvt.rna.tf32.f32 %0, %1;" : "=r"(u) : "f"(f));
    return u;
}

__device__ __forceinline__ void mma_tf32(float d[4], const unsigned a[4], const unsigned b[2]) {
    asm("mma.sync.aligned.m16n8k8.row.col.f32.tf32.tf32.f32 "
        "{%0,%1,%2,%3}, {%4,%5,%6,%7}, {%8,%9}, {%0,%1,%2,%3};"
        : "+f"(d[0]), "+f"(d[1]), "+f"(d[2]), "+f"(d[3])
        : "r"(a[0]), "r"(a[1]), "r"(a[2]), "r"(a[3]), "r"(b[0]), "r"(b[1]));
}

__global__ void __launch_bounds__(256, 2)
gemm_tc(const float* __restrict__ A, const float* __restrict__ Bw,
        const float* __restrict__ bias, const float* __restrict__ res,
        float* __restrict__ C,
        int M, int N, int K, int lda, int ldb, int ldc,
        int nb2,
        long long sA1, long long sA2, long long sB1, long long sB2,
        long long sC1, long long sC2, int relu)
{
    int z = blockIdx.z;
    int b1 = z / nb2, b2 = z - b1 * nb2;
    A  += (long long)b1 * sA1 + (long long)b2 * sA2;
    Bw += (long long)b1 * sB1 + (long long)b2 * sB2;
    long long co = (long long)b1 * sC1 + (long long)b2 * sC2;
    C += co;
    if (res) res += co;

    __shared__ float As[2][BM * ASTR];
    __shared__ float Bs[2][BK * BSTR];

    int tid = threadIdx.x;
    int warp = tid >> 5, lane = tid & 31;
    int wm = warp >> 2;            // 0..1 -> 64-row slab
    int wn = warp & 3;             // 0..3 -> 32-col slab
    int gid = lane >> 2, tig = lane & 3;
    int bm = blockIdx.y * BM, bn = blockIdx.x * BN;

    float acc[4][4][4];
#pragma unroll
    for (int i = 0; i < 4; i++)
#pragma unroll
        for (int j = 0; j < 4; j++)
#pragma unroll
            for (int l = 0; l < 4; l++) acc[i][j][l] = 0.f;

    // global tile coordinates for this thread's loads
    // A: 512 float4 per tile; idx = tid + 256*i -> row = idx>>2, c = idx&3
    // B: same mapping over n
    int ar0 = (tid * 1 + 0, (tid + 0) >> 2); // silence unused pattern
    (void)ar0;

    int nk = K / BK;

    // prologue: load tile 0 into buffer 0
    {
#pragma unroll
        for (int i = 0; i < 2; i++) {
            int idx = tid + 256 * i;
            int r = idx >> 2, c = idx & 3;
            float4 v = *(const float4*)&A[(long long)(bm + r) * lda + c * 4];
            As[0][r * ASTR + c * 4 + 0] = __uint_as_float(f2tf(v.x));
            As[0][r * ASTR + c * 4 + 1] = __uint_as_float(f2tf(v.y));
            As[0][r * ASTR + c * 4 + 2] = __uint_as_float(f2tf(v.z));
            As[0][r * ASTR + c * 4 + 3] = __uint_as_float(f2tf(v.w));
            float4 w = *(const float4*)&Bw[(long long)(bn + r) * ldb + c * 4];
            Bs[0][(c * 4 + 0) * BSTR + r] = __uint_as_float(f2tf(w.x));
            Bs[0][(c * 4 + 1) * BSTR + r] = __uint_as_float(f2tf(w.y));
            Bs[0][(c * 4 + 2) * BSTR + r] = __uint_as_float(f2tf(w.z));
            Bs[0][(c * 4 + 3) * BSTR + r] = __uint_as_float(f2tf(w.w));
        }
    }
    __syncthreads();

    for (int kt = 0; kt < nk; kt++) {
        int cur = kt & 1, nxt = cur ^ 1;
        float4 pa[2], pb[2];
        bool more = (kt + 1 < nk);
        if (more) {
            int k0 = (kt + 1) * BK;
#pragma unroll
            for (int i = 0; i < 2; i++) {
                int idx = tid + 256 * i;
                int r = idx >> 2, c = idx & 3;
                pa[i] = *(const float4*)&A[(long long)(bm + r) * lda + k0 + c * 4];
                pb[i] = *(const float4*)&Bw[(long long)(bn + r) * ldb + k0 + c * 4];
            }
        }

        // compute on cur: 2 k8-steps
#pragma unroll
        for (int ks = 0; ks < 2; ks++) {
            unsigned af[4][4], bf[4][2];
#pragma unroll
            for (int mt = 0; mt < 4; mt++) {
                int r = wm * 64 + mt * 16 + gid;
                af[mt][0] = __float_as_uint(As[cur][r * ASTR + ks * 8 + tig]);
                af[mt][1] = __float_as_uint(As[cur][(r + 8) * ASTR + ks * 8 + tig]);
                af[mt][2] = __float_as_uint(As[cur][r * ASTR + ks * 8 + tig + 4]);
                af[mt][3] = __float_as_uint(As[cur][(r + 8) * ASTR + ks * 8 + tig + 4]);
            }
#pragma unroll
            for (int nt = 0; nt < 4; nt++) {
                int n = wn * 32 + nt * 8 + gid;
                bf[nt][0] = __float_as_uint(Bs[cur][(ks * 8 + tig) * BSTR + n]);
                bf[nt][1] = __float_as_uint(Bs[cur][(ks * 8 + tig + 4) * BSTR + n]);
            }
#pragma unroll
            for (int mt = 0; mt < 4; mt++)
#pragma unroll
                for (int nt = 0; nt < 4; nt++)
                    mma_tf32(acc[mt][nt], af[mt], bf[nt]);
        }

        if (more) {
#pragma unroll
            for (int i = 0; i < 2; i++) {
                int idx = tid + 256 * i;
                int r = idx >> 2, c = idx & 3;
                As[nxt][r * ASTR + c * 4 + 0] = __uint_as_float(f2tf(pa[i].x));
                As[nxt][r * ASTR + c * 4 + 1] = __uint_as_float(f2tf(pa[i].y));
                As[nxt][r * ASTR + c * 4 + 2] = __uint_as_float(f2tf(pa[i].z));
                As[nxt][r * ASTR + c * 4 + 3] = __uint_as_float(f2tf(pa[i].w));
                Bs[nxt][(c * 4 + 0) * BSTR + r] = __uint_as_float(f2tf(pb[i].x));
                Bs[nxt][(c * 4 + 1) * BSTR + r] = __uint_as_float(f2tf(pb[i].y));
                Bs[nxt][(c * 4 + 2) * BSTR + r] = __uint_as_float(f2tf(pb[i].z));
                Bs[nxt][(c * 4 + 3) * BSTR + r] = __uint_as_float(f2tf(pb[i].w));
            }
            __syncthreads();
        }
    }

    // epilogue
#pragma unroll
    for (int mt = 0; mt < 4; mt++) {
        int row = bm + wm * 64 + mt * 16 + gid;
#pragma unroll
        for (int nt = 0; nt < 4; nt++) {
            int col = bn + wn * 32 + nt * 8 + tig * 2;
            float v0 = acc[mt][nt][0], v1 = acc[mt][nt][1];
            float v2 = acc[mt][nt][2], v3 = acc[mt][nt][3];
            if (bias) {
                float b0 = bias[col], b1 = bias[col + 1];
                v0 += b0; v1 += b1; v2 += b0; v3 += b1;
            }
            if (res) {
                const float2 r0 = *(const float2*)&res[(long long)row * ldc + col];
                const float2 r1 = *(const float2*)&res[(long long)(row + 8) * ldc + col];
                v0 += r0.x; v1 += r0.y; v2 += r1.x; v3 += r1.y;
            }
            if (relu) {
                v0 = fmaxf(v0, 0.f); v1 = fmaxf(v1, 0.f);
                v2 = fmaxf(v2, 0.f); v3 = fmaxf(v3, 0.f);
            }
            *(float2*)&C[(long long)row * ldc + col] = make_float2(v0, v1);
            *(float2*)&C[(long long)(row + 8) * ldc + col] = make_float2(v2, v3);
        }
    }
}

// ---------------- LayerNorm: one block per row ----------------
__global__ void ln_kernel(const float* __restrict__ x, const float* __restrict__ w,
                          const float* __restrict__ bp, float* __restrict__ y, int D)
{
    long long row = blockIdx.x;
    const float* xr = x + row * D;
    float* yr = y + row * D;
    __shared__ float red[256];
    int tid = threadIdx.x;
    int n = D >> 8;
    float vals[2];
    float s = 0.f, sq = 0.f;
    for (int i = 0; i < n; i++) {
        float t = xr[tid + i * 256];
        vals[i] = t; s += t; sq += t * t;
    }
    red[tid] = s; __syncthreads();
    for (int off = 128; off; off >>= 1) { if (tid < off) red[tid] += red[tid + off]; __syncthreads(); }
    float mean = red[0] / D; __syncthreads();
    red[tid] = sq; __syncthreads();
    for (int off = 128; off; off >>= 1) { if (tid < off) red[tid] += red[tid + off]; __syncthreads(); }
    float var = red[0] / D - mean * mean;
    float inv = rsqrtf(var + 1e-6f);
    for (int i = 0; i < n; i++) {
        int c = tid + i * 256;
        yr[c] = (vals[i] - mean) * inv * w[c] + bp[c];
    }
}

// ---------------- causal flash attention (D=32), 64 q-rows per block ----------------
__global__ void attn_kernel(const float* __restrict__ qkv, float* __restrict__ O)
{
    int qb = blockIdx.x;
    int bh = blockIdx.y;
    int b = bh >> 3, hh = bh & 7;
    int tid = threadIdx.x;
    int tx = tid & 15, ty = tid >> 4;

    __shared__ float Qs[64][33], Ks[64][33], Vs[64][33];
    __shared__ float Ps[64][65];

#pragma unroll
    for (int i = 0; i < 8; i++) {
        int idx = tid + i * 256;
        int r = idx >> 5, d = idx & 31;
        Qs[r][d] = qkv[((long long)(b * TT + qb * 64 + r) * 768) + hh * 32 + d];
    }

    float m_i[4], l_i[4], oacc[4][2];
#pragma unroll
    for (int i = 0; i < 4; i++) { m_i[i] = -1e30f; l_i[i] = 0.f; oacc[i][0] = 0.f; oacc[i][1] = 0.f; }

    const float scale = 0.17677669529663687f;

    for (int kb = 0; kb <= qb; kb++) {
        __syncthreads();
#pragma unroll
        for (int i = 0; i < 8; i++) {
            int idx = tid + i * 256;
            int r = idx >> 5, d = idx & 31;
            long long base = (long long)(b * TT + kb * 64 + r) * 768 + hh * 32 + d;
            Ks[r][d] = qkv[base + 256];
            Vs[r][d] = qkv[base + 512];
        }
        __syncthreads();

        float s[4][4];
#pragma unroll
        for (int i = 0; i < 4; i++)
#pragma unroll
            for (int j = 0; j < 4; j++) s[i][j] = 0.f;
#pragma unroll
        for (int d = 0; d < 32; d++) {
            float a[4], bb[4];
#pragma unroll
            for (int i = 0; i < 4; i++) a[i] = Qs[ty * 4 + i][d];
#pragma unroll
            for (int j = 0; j < 4; j++) bb[j] = Ks[tx * 4 + j][d];
#pragma unroll
            for (int i = 0; i < 4; i++)
#pragma unroll
                for (int j = 0; j < 4; j++) s[i][j] += a[i] * bb[j];
        }
        if (kb == qb) {
#pragma unroll
            for (int i = 0; i < 4; i++)
#pragma unroll
                for (int j = 0; j < 4; j++)
                    s[i][j] = (tx * 4 + j > ty * 4 + i) ? -1e30f : s[i][j] * scale;
        } else {
#pragma unroll
            for (int i = 0; i < 4; i++)
#pragma unroll
                for (int j = 0; j < 4; j++) s[i][j] *= scale;
        }

#pragma unroll
        for (int i = 0; i < 4; i++) {
            float rmax = fmaxf(fmaxf(s[i][0], s[i][1]), fmaxf(s[i][2], s[i][3]));
#pragma unroll
            for (int off = 8; off; off >>= 1)
                rmax = fmaxf(rmax, __shfl_xor_sync(0xffffffffu, rmax, off));
            float newm = fmaxf(m_i[i], rmax);
            float alpha = __expf(m_i[i] - newm);
            float rsum = 0.f;
#pragma unroll
            for (int j = 0; j < 4; j++) {
                float p = __expf(s[i][j] - newm);
                s[i][j] = p; rsum += p;
            }
#pragma unroll
            for (int off = 8; off; off >>= 1)
                rsum += __shfl_xor_sync(0xffffffffu, rsum, off);
            l_i[i] = l_i[i] * alpha + rsum;
            m_i[i] = newm;
            oacc[i][0] *= alpha; oacc[i][1] *= alpha;
#pragma unroll
            for (int j = 0; j < 4; j++) Ps[ty * 4 + i][tx * 4 + j] = s[i][j];
        }
        __syncthreads();
#pragma unroll
        for (int ss = 0; ss < 64; ss++) {
            float v0 = Vs[ss][tx * 2], v1 = Vs[ss][tx * 2 + 1];
#pragma unroll
            for (int i = 0; i < 4; i++) {
                float p = Ps[ty * 4 + i][ss];
                oacc[i][0] += p * v0;
                oacc[i][1] += p * v1;
            }
        }
    }

#pragma unroll
    for (int i = 0; i < 4; i++) {
        int t = qb * 64 + ty * 4 + i;
        float invl = 1.f / l_i[i];
        O[((long long)(b * TT + t) * CC) + hh * 32 + tx * 2 + 0] = oacc[i][0] * invl;
        O[((long long)(b * TT + t) * CC) + hh * 32 + tx * 2 + 1] = oacc[i][1] * invl;
    }
}

// ---------------- spatial softmax over e + mean over heads ----------------
__global__ void smax_mean_kernel(const float* __restrict__ sc, float* __restrict__ sw)
{
    int bc = blockIdx.x;
    int b = bc >> 8, c = bc & 255;
    int e = threadIdx.x;
    __shared__ float red[256];
    float acc = 0.f;
    for (int h = 0; h < 8; h++) {
        float v = sc[(((long long)(b * 8 + h) * CC + c) * CC) + e] * 0.125f;
        red[e] = v; __syncthreads();
        for (int off = 128; off; off >>= 1) { if (e < off) red[e] = fmaxf(red[e], red[e + off]); __syncthreads(); }
        float mx = red[0]; __syncthreads();
        float ev = __expf(v - mx);
        red[e] = ev; __syncthreads();
        for (int off = 128; off; off >>= 1) { if (e < off) red[e] += red[e + off]; __syncthreads(); }
        float sm = red[0]; __syncthreads();
        acc += ev / sm;
    }
    sw[(long long)bc * CC + e] = acc * 0.125f;
}

// ---------------- host launch ----------------
static void gemm(const float* A, const float* Bw, const float* bias, const float* res, float* C,
                 int M, int N, int K, int lda, int ldb, int ldc,
                 int nbatch, int nb2,
                 long long sA1, long long sA2, long long sB1, long long sB2,
                 long long sC1, long long sC2, int relu)
{
    dim3 grid(N / BN, M / BM, nbatch);
    gemm_tc<<<grid, 256>>>(A, Bw, bias, res, C, M, N, K, lda, ldb, ldc,
                           nb2, sA1, sA2, sB1, sB2, sC1, sC2, relu);
}

extern "C" void kernel_launch(void* const* d_in, const int* in_sizes, int n_in,
                              void* d_out, int out_size)
{
    const float* x_T     = (const float*)d_in[0];
    const float* x_S     = (const float*)d_in[1];
    const float* Wq_t    = (const float*)d_in[2];
    const float* Wk_t    = (const float*)d_in[3];
    const float* Wv_t    = (const float*)d_in[4];
    const float* Wo      = (const float*)d_in[5];
    const float* Wq_s    = (const float*)d_in[6];
    const float* Wk_s    = (const float*)d_in[7];
    const float* ff1_w1  = (const float*)d_in[8];
    const float* ff1_b1  = (const float*)d_in[9];
    const float* ff1_w2  = (const float*)d_in[10];
    const float* ff1_b2  = (const float*)d_in[11];
    const float* ff2_w1  = (const float*)d_in[12];
    const float* ff2_b1  = (const float*)d_in[13];
    const float* ff2_w2  = (const float*)d_in[14];
    const float* ff2_b2  = (const float*)d_in[15];
    const float* t_ln1_w = (const float*)d_in[16];
    const float* t_ln1_b = (const float*)d_in[17];
    const float* t_ln2_w = (const float*)d_in[18];
    const float* t_ln2_b = (const float*)d_in[19];
    const float* s_ln1_w = (const float*)d_in[20];
    const float* s_ln1_b = (const float*)d_in[21];
    const float* fus_ln_w= (const float*)d_in[22];
    const float* fus_ln_b= (const float*)d_in[23];

    float *h, *qkv, *o, *x, *u, *to, *hs, *qks, *sc, *x2, *wqkv, *wqks;
    cudaGetSymbolAddress((void**)&h,    g_h);
    cudaGetSymbolAddress((void**)&qkv,  g_qkv);
    cudaGetSymbolAddress((void**)&o,    g_o);
    cudaGetSymbolAddress((void**)&x,    g_x);
    cudaGetSymbolAddress((void**)&u,    g_u);
    cudaGetSymbolAddress((void**)&to,   g_to);
    cudaGetSymbolAddress((void**)&hs,   g_hs);
    cudaGetSymbolAddress((void**)&qks,  g_qks);
    cudaGetSymbolAddress((void**)&sc,   g_sc);
    cudaGetSymbolAddress((void**)&x2,   g_x2);
    cudaGetSymbolAddress((void**)&wqkv, g_wqkv);
    cudaGetSymbolAddress((void**)&wqks, g_wqks);

    float* out = (float*)d_out;                 // [B,T,C]
    float* sw  = out + (long long)ROWS_T * CC;  // spatial_weights [B,C,C]

    // pack weights: Wqkv = [768,256], Wqks = [1024,512] (row n-major already)
    cudaMemcpyAsync(wqkv,           Wq_t, 256 * 256 * 4, cudaMemcpyDeviceToDevice, 0);
    cudaMemcpyAsync(wqkv + 256*256, Wk_t, 256 * 256 * 4, cudaMemcpyDeviceToDevice, 0);
    cudaMemcpyAsync(wqkv + 512*256, Wv_t, 256 * 256 * 4, cudaMemcpyDeviceToDevice, 0);
    cudaMemcpyAsync(wqks,           Wq_s, 512 * 512 * 4, cudaMemcpyDeviceToDevice, 0);
    cudaMemcpyAsync(wqks + 512*512, Wk_s, 512 * 512 * 4, cudaMemcpyDeviceToDevice, 0);

    // ---- temporal branch ----
    ln_kernel<<<ROWS_T, 256>>>(x_T, t_ln1_w, t_ln1_b, h, CC);
    gemm(h, wqkv, 0, 0, qkv, ROWS_T, 768, CC, CC, CC, 768, 1,1, 0,0,0,0,0,0, 0);
    attn_kernel<<<dim3(TT/64, BB*HH), 256>>>(qkv, o);
    gemm(o, Wo, 0, x_T, x, ROWS_T, CC, CC, CC, CC, CC, 1,1, 0,0,0,0,0,0, 0);
    ln_kernel<<<ROWS_T, 256>>>(x, t_ln2_w, t_ln2_b, h, CC);
    gemm(h, ff1_w1, ff1_b1, 0, u,  ROWS_T, 4*CC, CC, CC, CC, 4*CC, 1,1, 0,0,0,0,0,0, 1);
    gemm(u, ff1_w2, ff1_b2, x, to, ROWS_T, CC, 4*CC, 4*CC, 4*CC, CC, 1,1, 0,0,0,0,0,0, 0);

    // ---- spatial branch ----
    ln_kernel<<<ROWS_S, 256>>>(x_S, s_ln1_w, s_ln1_b, hs, TT);
    gemm(hs, wqks, 0, 0, qks, ROWS_S, 1024, TT, TT, TT, 1024, 1,1, 0,0,0,0,0,0, 0);
    // sc[b,h] = qs[b,h] @ ks[b,h]^T
    gemm(qks, qks + 512, 0, 0, sc, CC, CC, HS_S, 1024, 1024, CC,
         BB*HH, HH,
         (long long)CC*1024, 64, (long long)CC*1024, 64,
         (long long)HH*CC*CC, (long long)CC*CC, 0);
    smax_mean_kernel<<<BB*CC, 256>>>(sc, sw);

    // ---- fusion: x2 = TO + TO @ sw^T (batched over b) ----
    gemm(to, sw, 0, to, x2, TT, CC, CC, CC, CC, CC,
         BB, 1,
         (long long)TT*CC, 0, (long long)CC*CC, 0, (long long)TT*CC, 0, 0);

    // ---- FFN2 -> out ----
    ln_kernel<<<ROWS_T, 256>>>(x2, fus_ln_w, fus_ln_b, h, CC);
    gemm(h, ff2_w1, ff2_b1, 0, u, ROWS_T, 4*CC, CC, CC, CC, 4*CC, 1,1, 0,0,0,0,0,0, 1);
    gemm(u, ff2_w2, ff2_b2, x2, out, ROWS_T, CC, 4*CC, 4*CC, 4*CC, CC, 1,1, 0,0,0,0,0,0, 0);
}

// round 3
// speedup vs baseline: 3.3572x; 1.2157x over previous
#include <cuda_runtime.h>
#include <math.h>

// Problem constants
#define BB 16
#define TT 512
#define CC 256
#define HH 8
#define HS_T 32
#define HS_S 64
#define ROWS_T (BB*TT)      // 8192
#define ROWS_S (BB*CC)      // 4096

// ---------------- scratch (device globals; no allocation allowed) ----------------
__device__ float g_h[ROWS_T*CC];
__device__ float g_qkv[ROWS_T*3*CC];
__device__ float g_o[ROWS_T*CC];
__device__ float g_x[ROWS_T*CC];
__device__ float g_u[ROWS_T*4*CC];
__device__ float g_to[ROWS_T*CC];
__device__ float g_hs[ROWS_S*TT];
__device__ float g_qks[ROWS_S*2*512];
__device__ float g_sc[BB*HH*CC*CC];
__device__ float g_x2[ROWS_T*CC];
__device__ float g_wqkv[768*256];
__device__ float g_wqks[1024*512];

__device__ __forceinline__ unsigned f2tf(float f) {
    unsigned u;
    asm("cvt.rna.tf32.f32 %0, %1;" : "=r"(u) : "f"(f));
    return u;
}

__device__ __forceinline__ void mma_tf32(float d[4], const unsigned a[4], const unsigned b[2]) {
    asm("mma.sync.aligned.m16n8k8.row.col.f32.tf32.tf32.f32 "
        "{%0,%1,%2,%3}, {%4,%5,%6,%7}, {%8,%9}, {%0,%1,%2,%3};"
        : "+f"(d[0]), "+f"(d[1]), "+f"(d[2]), "+f"(d[3])
        : "r"(a[0]), "r"(a[1]), "r"(a[2]), "r"(a[3]), "r"(b[0]), "r"(b[1]));
}

// ================= tf32 tensor-core GEMM:  C = A @ B^T (+bias,+res,relu) =========
#define BM 128
#define BN 128
#define BK 16
#define ASTR 20
#define BSTR 136

__global__ void __launch_bounds__(256, 2)
gemm_tc(const float* __restrict__ A, const float* __restrict__ Bw,
        const float* __restrict__ bias, const float* __restrict__ res,
        float* __restrict__ C,
        int M, int N, int K, int lda, int ldb, int ldc,
        int nb2,
        long long sA1, long long sA2, long long sB1, long long sB2,
        long long sC1, long long sC2, int relu)
{
    int z = blockIdx.z;
    int b1 = z / nb2, b2 = z - b1 * nb2;
    A  += (long long)b1 * sA1 + (long long)b2 * sA2;
    Bw += (long long)b1 * sB1 + (long long)b2 * sB2;
    long long co = (long long)b1 * sC1 + (long long)b2 * sC2;
    C += co;
    if (res) res += co;

    __shared__ float As[2][BM * ASTR];
    __shared__ float Bs[2][BK * BSTR];

    int tid = threadIdx.x;
    int warp = tid >> 5, lane = tid & 31;
    int wm = warp >> 2;
    int wn = warp & 3;
    int gid = lane >> 2, tig = lane & 3;
    int bm = blockIdx.y * BM, bn = blockIdx.x * BN;

    float acc[4][4][4];
#pragma unroll
    for (int i = 0; i < 4; i++)
#pragma unroll
        for (int j = 0; j < 4; j++)
#pragma unroll
            for (int l = 0; l < 4; l++) acc[i][j][l] = 0.f;

    int nk = K / BK;

    {
#pragma unroll
        for (int i = 0; i < 2; i++) {
            int idx = tid + 256 * i;
            int r = idx >> 2, c = idx & 3;
            float4 v = *(const float4*)&A[(long long)(bm + r) * lda + c * 4];
            As[0][r * ASTR + c * 4 + 0] = __uint_as_float(f2tf(v.x));
            As[0][r * ASTR + c * 4 + 1] = __uint_as_float(f2tf(v.y));
            As[0][r * ASTR + c * 4 + 2] = __uint_as_float(f2tf(v.z));
            As[0][r * ASTR + c * 4 + 3] = __uint_as_float(f2tf(v.w));
            float4 w = *(const float4*)&Bw[(long long)(bn + r) * ldb + c * 4];
            Bs[0][(c * 4 + 0) * BSTR + r] = __uint_as_float(f2tf(w.x));
            Bs[0][(c * 4 + 1) * BSTR + r] = __uint_as_float(f2tf(w.y));
            Bs[0][(c * 4 + 2) * BSTR + r] = __uint_as_float(f2tf(w.z));
            Bs[0][(c * 4 + 3) * BSTR + r] = __uint_as_float(f2tf(w.w));
        }
    }
    __syncthreads();

    for (int kt = 0; kt < nk; kt++) {
        int cur = kt & 1, nxt = cur ^ 1;
        float4 pa[2], pb[2];
        bool more = (kt + 1 < nk);
        if (more) {
            int k0 = (kt + 1) * BK;
#pragma unroll
            for (int i = 0; i < 2; i++) {
                int idx = tid + 256 * i;
                int r = idx >> 2, c = idx & 3;
                pa[i] = *(const float4*)&A[(long long)(bm + r) * lda + k0 + c * 4];
                pb[i] = *(const float4*)&Bw[(long long)(bn + r) * ldb + k0 + c * 4];
            }
        }

#pragma unroll
        for (int ks = 0; ks < 2; ks++) {
            unsigned af[4][4], bf[4][2];
#pragma unroll
            for (int mt = 0; mt < 4; mt++) {
                int r = wm * 64 + mt * 16 + gid;
                af[mt][0] = __float_as_uint(As[cur][r * ASTR + ks * 8 + tig]);
                af[mt][1] = __float_as_uint(As[cur][(r + 8) * ASTR + ks * 8 + tig]);
                af[mt][2] = __float_as_uint(As[cur][r * ASTR + ks * 8 + tig + 4]);
                af[mt][3] = __float_as_uint(As[cur][(r + 8) * ASTR + ks * 8 + tig + 4]);
            }
#pragma unroll
            for (int nt = 0; nt < 4; nt++) {
                int n = wn * 32 + nt * 8 + gid;
                bf[nt][0] = __float_as_uint(Bs[cur][(ks * 8 + tig) * BSTR + n]);
                bf[nt][1] = __float_as_uint(Bs[cur][(ks * 8 + tig + 4) * BSTR + n]);
            }
#pragma unroll
            for (int mt = 0; mt < 4; mt++)
#pragma unroll
                for (int nt = 0; nt < 4; nt++)
                    mma_tf32(acc[mt][nt], af[mt], bf[nt]);
        }

        if (more) {
#pragma unroll
            for (int i = 0; i < 2; i++) {
                int idx = tid + 256 * i;
                int r = idx >> 2, c = idx & 3;
                As[nxt][r * ASTR + c * 4 + 0] = __uint_as_float(f2tf(pa[i].x));
                As[nxt][r * ASTR + c * 4 + 1] = __uint_as_float(f2tf(pa[i].y));
                As[nxt][r * ASTR + c * 4 + 2] = __uint_as_float(f2tf(pa[i].z));
                As[nxt][r * ASTR + c * 4 + 3] = __uint_as_float(f2tf(pa[i].w));
                Bs[nxt][(c * 4 + 0) * BSTR + r] = __uint_as_float(f2tf(pb[i].x));
                Bs[nxt][(c * 4 + 1) * BSTR + r] = __uint_as_float(f2tf(pb[i].y));
                Bs[nxt][(c * 4 + 2) * BSTR + r] = __uint_as_float(f2tf(pb[i].z));
                Bs[nxt][(c * 4 + 3) * BSTR + r] = __uint_as_float(f2tf(pb[i].w));
            }
            __syncthreads();
        }
    }

#pragma unroll
    for (int mt = 0; mt < 4; mt++) {
        int row = bm + wm * 64 + mt * 16 + gid;
#pragma unroll
        for (int nt = 0; nt < 4; nt++) {
            int col = bn + wn * 32 + nt * 8 + tig * 2;
            float v0 = acc[mt][nt][0], v1 = acc[mt][nt][1];
            float v2 = acc[mt][nt][2], v3 = acc[mt][nt][3];
            if (bias) {
                float b0 = bias[col], b1 = bias[col + 1];
                v0 += b0; v1 += b1; v2 += b0; v3 += b1;
            }
            if (res) {
                const float2 r0 = *(const float2*)&res[(long long)row * ldc + col];
                const float2 r1 = *(const float2*)&res[(long long)(row + 8) * ldc + col];
                v0 += r0.x; v1 += r0.y; v2 += r1.x; v3 += r1.y;
            }
            if (relu) {
                v0 = fmaxf(v0, 0.f); v1 = fmaxf(v1, 0.f);
                v2 = fmaxf(v2, 0.f); v3 = fmaxf(v3, 0.f);
            }
            *(float2*)&C[(long long)row * ldc + col] = make_float2(v0, v1);
            *(float2*)&C[(long long)(row + 8) * ldc + col] = make_float2(v2, v3);
        }
    }
}

// ---------------- LayerNorm ----------------
__global__ void ln_kernel(const float* __restrict__ x, const float* __restrict__ w,
                          const float* __restrict__ bp, float* __restrict__ y, int D)
{
    long long row = blockIdx.x;
    const float* xr = x + row * D;
    float* yr = y + row * D;
    __shared__ float red[256];
    int tid = threadIdx.x;
    int n = D >> 8;
    float vals[2];
    float s = 0.f, sq = 0.f;
    for (int i = 0; i < n; i++) {
        float t = xr[tid + i * 256];
        vals[i] = t; s += t; sq += t * t;
    }
    red[tid] = s; __syncthreads();
    for (int off = 128; off; off >>= 1) { if (tid < off) red[tid] += red[tid + off]; __syncthreads(); }
    float mean = red[0] / D; __syncthreads();
    red[tid] = sq; __syncthreads();
    for (int off = 128; off; off >>= 1) { if (tid < off) red[tid] += red[tid + off]; __syncthreads(); }
    float var = red[0] / D - mean * mean;
    float inv = rsqrtf(var + 1e-6f);
    for (int i = 0; i < n; i++) {
        int c = tid + i * 256;
        yr[c] = (vals[i] - mean) * inv * w[c] + bp[c];
    }
}

// ============ tensor-core causal flash attention (D=32) ============
// 4 warps/block, 64 q-rows per block (16 per warp). grid = (T/64, B*H).
// qkv layout [B,T,768]: q @ h*32, k @ 256+h*32, v @ 512+h*32.
#define PSTR 68
__global__ void __launch_bounds__(128)
attn_tc(const float* __restrict__ qkv, float* __restrict__ O)
{
    int qb = blockIdx.x;            // 0..7
    int bh = blockIdx.y;            // 0..127
    int b = bh >> 3, hh = bh & 7;
    int tid = threadIdx.x, warp = tid >> 5, lane = tid & 31;
    int gid = lane >> 2, tig = lane & 3;

    __shared__ float Ks[64][36];
    __shared__ float Vs[64][36];
    __shared__ float Ps[4][16][PSTR];

    int qrow = qb * 64 + warp * 16;
    const float* Qb = qkv + (long long)(b * TT + qrow) * 768 + hh * 32;

    unsigned qf[4][4];
#pragma unroll
    for (int ks = 0; ks < 4; ks++) {
        qf[ks][0] = f2tf(Qb[gid * 768 + ks * 8 + tig]);
        qf[ks][1] = f2tf(Qb[(gid + 8) * 768 + ks * 8 + tig]);
        qf[ks][2] = f2tf(Qb[gid * 768 + ks * 8 + tig + 4]);
        qf[ks][3] = f2tf(Qb[(gid + 8) * 768 + ks * 8 + tig + 4]);
    }

    float m0 = -1e30f, m1 = -1e30f, l0 = 0.f, l1 = 0.f;
    float oacc[4][4];
#pragma unroll
    for (int i = 0; i < 4; i++)
#pragma unroll
        for (int j = 0; j < 4; j++) oacc[i][j] = 0.f;

    const float scale = 0.17677669529663687f; // 1/sqrt(32)

    for (int kb = 0; kb <= qb; kb++) {
        __syncthreads();
#pragma unroll
        for (int i = 0; i < 4; i++) {
            int idx = tid + 128 * i;        // 512 float4 slots
            int r = idx >> 3, c4 = idx & 7;
            const float* p = qkv + (long long)(b * TT + kb * 64 + r) * 768 + 256 + hh * 32 + c4 * 4;
            float4 kv = *(const float4*)p;
            float4 vv = *(const float4*)(p + 256);
            Ks[r][c4 * 4 + 0] = __uint_as_float(f2tf(kv.x));
            Ks[r][c4 * 4 + 1] = __uint_as_float(f2tf(kv.y));
            Ks[r][c4 * 4 + 2] = __uint_as_float(f2tf(kv.z));
            Ks[r][c4 * 4 + 3] = __uint_as_float(f2tf(kv.w));
            Vs[r][c4 * 4 + 0] = __uint_as_float(f2tf(vv.x));
            Vs[r][c4 * 4 + 1] = __uint_as_float(f2tf(vv.y));
            Vs[r][c4 * 4 + 2] = __uint_as_float(f2tf(vv.z));
            Vs[r][c4 * 4 + 3] = __uint_as_float(f2tf(vv.w));
        }
        __syncthreads();

        // S = Q @ K^T : per-warp 16x64 tile
        float sacc[8][4];
#pragma unroll
        for (int nt = 0; nt < 8; nt++)
#pragma unroll
            for (int c = 0; c < 4; c++) sacc[nt][c] = 0.f;
#pragma unroll
        for (int ks = 0; ks < 4; ks++) {
#pragma unroll
            for (int nt = 0; nt < 8; nt++) {
                unsigned bb[2];
                bb[0] = __float_as_uint(Ks[nt * 8 + gid][ks * 8 + tig]);
                bb[1] = __float_as_uint(Ks[nt * 8 + gid][ks * 8 + tig + 4]);
                mma_tf32(sacc[nt], qf[ks], bb);
            }
        }

        bool diag = (kb == qb);
        int row0 = qrow + gid, row1 = row0 + 8;
        float rmax0 = -1e30f, rmax1 = -1e30f;
#pragma unroll
        for (int nt = 0; nt < 8; nt++) {
            int colb = kb * 64 + nt * 8 + tig * 2;
            float s0 = sacc[nt][0] * scale;
            float s1 = sacc[nt][1] * scale;
            float s2 = sacc[nt][2] * scale;
            float s3 = sacc[nt][3] * scale;
            if (diag) {
                if (colb     > row0) s0 = -1e30f;
                if (colb + 1 > row0) s1 = -1e30f;
                if (colb     > row1) s2 = -1e30f;
                if (colb + 1 > row1) s3 = -1e30f;
            }
            sacc[nt][0] = s0; sacc[nt][1] = s1; sacc[nt][2] = s2; sacc[nt][3] = s3;
            rmax0 = fmaxf(rmax0, fmaxf(s0, s1));
            rmax1 = fmaxf(rmax1, fmaxf(s2, s3));
        }
        rmax0 = fmaxf(rmax0, __shfl_xor_sync(0xffffffffu, rmax0, 1));
        rmax0 = fmaxf(rmax0, __shfl_xor_sync(0xffffffffu, rmax0, 2));
        rmax1 = fmaxf(rmax1, __shfl_xor_sync(0xffffffffu, rmax1, 1));
        rmax1 = fmaxf(rmax1, __shfl_xor_sync(0xffffffffu, rmax1, 2));

        float newm0 = fmaxf(m0, rmax0), newm1 = fmaxf(m1, rmax1);
        float a0 = __expf(m0 - newm0), a1 = __expf(m1 - newm1);
        m0 = newm0; m1 = newm1;

        float ls0 = 0.f, ls1 = 0.f;
#pragma unroll
        for (int nt = 0; nt < 8; nt++) {
            float p0 = __expf(sacc[nt][0] - newm0);
            float p1 = __expf(sacc[nt][1] - newm0);
            float p2 = __expf(sacc[nt][2] - newm1);
            float p3 = __expf(sacc[nt][3] - newm1);
            ls0 += p0 + p1; ls1 += p2 + p3;
            Ps[warp][gid][nt * 8 + tig * 2]         = __uint_as_float(f2tf(p0));
            Ps[warp][gid][nt * 8 + tig * 2 + 1]     = __uint_as_float(f2tf(p1));
            Ps[warp][gid + 8][nt * 8 + tig * 2]     = __uint_as_float(f2tf(p2));
            Ps[warp][gid + 8][nt * 8 + tig * 2 + 1] = __uint_as_float(f2tf(p3));
        }
        ls0 += __shfl_xor_sync(0xffffffffu, ls0, 1);
        ls0 += __shfl_xor_sync(0xffffffffu, ls0, 2);
        ls1 += __shfl_xor_sync(0xffffffffu, ls1, 1);
        ls1 += __shfl_xor_sync(0xffffffffu, ls1, 2);
        l0 = l0 * a0 + ls0;
        l1 = l1 * a1 + ls1;
#pragma unroll
        for (int nt = 0; nt < 4; nt++) {
            oacc[nt][0] *= a0; oacc[nt][1] *= a0;
            oacc[nt][2] *= a1; oacc[nt][3] *= a1;
        }
        __syncwarp();

        // O += P @ V
#pragma unroll
        for (int ks2 = 0; ks2 < 8; ks2++) {
            unsigned af[4];
            af[0] = __float_as_uint(Ps[warp][gid][ks2 * 8 + tig]);
            af[1] = __float_as_uint(Ps[warp][gid + 8][ks2 * 8 + tig]);
            af[2] = __float_as_uint(Ps[warp][gid][ks2 * 8 + tig + 4]);
            af[3] = __float_as_uint(Ps[warp][gid + 8][ks2 * 8 + tig + 4]);
#pragma unroll
            for (int nt2 = 0; nt2 < 4; nt2++) {
                unsigned bb[2];
                bb[0] = __float_as_uint(Vs[ks2 * 8 + tig][nt2 * 8 + gid]);
                bb[1] = __float_as_uint(Vs[ks2 * 8 + tig + 4][nt2 * 8 + gid]);
                mma_tf32(oacc[nt2], af, bb);
            }
        }
    }

    float invl0 = 1.f / l0, invl1 = 1.f / l1;
#pragma unroll
    for (int nt2 = 0; nt2 < 4; nt2++) {
        int col = hh * 32 + nt2 * 8 + tig * 2;
        long long o0 = (long long)(b * TT + qrow + gid) * CC + col;
        long long o1 = (long long)(b * TT + qrow + gid + 8) * CC + col;
        *(float2*)&O[o0] = make_float2(oacc[nt2][0] * invl0, oacc[nt2][1] * invl0);
        *(float2*)&O[o1] = make_float2(oacc[nt2][2] * invl1, oacc[nt2][3] * invl1);
    }
}

// ---------------- spatial softmax over e + mean over heads (warp per head) -------
__global__ void __launch_bounds__(256)
smax_mean_kernel(const float* __restrict__ sc, float* __restrict__ sw)
{
    int bc = blockIdx.x;            // b*256 + c
    int b = bc >> 8, c = bc & 255;
    int warp = threadIdx.x >> 5, lane = threadIdx.x & 31;
    __shared__ float buf[8][256];

    const float* row = sc + (((long long)(b * 8 + warp) * CC + c) * CC);
    float4 v0 = *(const float4*)&row[lane * 8];
    float4 v1 = *(const float4*)&row[lane * 8 + 4];
    float vals[8] = {v0.x, v0.y, v0.z, v0.w, v1.x, v1.y, v1.z, v1.w};
    float mx = -1e30f;
#pragma unroll
    for (int i = 0; i < 8; i++) { vals[i] *= 0.125f; mx = fmaxf(mx, vals[i]); }
#pragma unroll
    for (int off = 16; off; off >>= 1)
        mx = fmaxf(mx, __shfl_xor_sync(0xffffffffu, mx, off));
    float s = 0.f;
    float ev[8];
#pragma unroll
    for (int i = 0; i < 8; i++) { ev[i] = __expf(vals[i] - mx); s += ev[i]; }
#pragma unroll
    for (int off = 16; off; off >>= 1)
        s += __shfl_xor_sync(0xffffffffu, s, off);
    float inv = 0.125f / s;
    float4 w0 = make_float4(ev[0] * inv, ev[1] * inv, ev[2] * inv, ev[3] * inv);
    float4 w1 = make_float4(ev[4] * inv, ev[5] * inv, ev[6] * inv, ev[7] * inv);
    *(float4*)&buf[warp][lane * 8] = w0;
    *(float4*)&buf[warp][lane * 8 + 4] = w1;
    __syncthreads();
    int e = threadIdx.x;
    float acc = 0.f;
#pragma unroll
    for (int h = 0; h < 8; h++) acc += buf[h][e];
    sw[(long long)bc * CC + e] = acc;
}

// ---------------- host launch ----------------
static void gemm(const float* A, const float* Bw, const float* bias, const float* res, float* C,
                 int M, int N, int K, int lda, int ldb, int ldc,
                 int nbatch, int nb2,
                 long long sA1, long long sA2, long long sB1, long long sB2,
                 long long sC1, long long sC2, int relu)
{
    dim3 grid(N / BN, M / BM, nbatch);
    gemm_tc<<<grid, 256>>>(A, Bw, bias, res, C, M, N, K, lda, ldb, ldc,
                           nb2, sA1, sA2, sB1, sB2, sC1, sC2, relu);
}

extern "C" void kernel_launch(void* const* d_in, const int* in_sizes, int n_in,
                              void* d_out, int out_size)
{
    const float* x_T     = (const float*)d_in[0];
    const float* x_S     = (const float*)d_in[1];
    const float* Wq_t    = (const float*)d_in[2];
    const float* Wk_t    = (const float*)d_in[3];
    const float* Wv_t    = (const float*)d_in[4];
    const float* Wo      = (const float*)d_in[5];
    const float* Wq_s    = (const float*)d_in[6];
    const float* Wk_s    = (const float*)d_in[7];
    const float* ff1_w1  = (const float*)d_in[8];
    const float* ff1_b1  = (const float*)d_in[9];
    const float* ff1_w2  = (const float*)d_in[10];
    const float* ff1_b2  = (const float*)d_in[11];
    const float* ff2_w1  = (const float*)d_in[12];
    const float* ff2_b1  = (const float*)d_in[13];
    const float* ff2_w2  = (const float*)d_in[14];
    const float* ff2_b2  = (const float*)d_in[15];
    const float* t_ln1_w = (const float*)d_in[16];
    const float* t_ln1_b = (const float*)d_in[17];
    const float* t_ln2_w = (const float*)d_in[18];
    const float* t_ln2_b = (const float*)d_in[19];
    const float* s_ln1_w = (const float*)d_in[20];
    const float* s_ln1_b = (const float*)d_in[21];
    const float* fus_ln_w= (const float*)d_in[22];
    const float* fus_ln_b= (const float*)d_in[23];

    float *h, *qkv, *o, *x, *u, *to, *hs, *qks, *sc, *x2, *wqkv, *wqks;
    cudaGetSymbolAddress((void**)&h,    g_h);
    cudaGetSymbolAddress((void**)&qkv,  g_qkv);
    cudaGetSymbolAddress((void**)&o,    g_o);
    cudaGetSymbolAddress((void**)&x,    g_x);
    cudaGetSymbolAddress((void**)&u,    g_u);
    cudaGetSymbolAddress((void**)&to,   g_to);
    cudaGetSymbolAddress((void**)&hs,   g_hs);
    cudaGetSymbolAddress((void**)&qks,  g_qks);
    cudaGetSymbolAddress((void**)&sc,   g_sc);
    cudaGetSymbolAddress((void**)&x2,   g_x2);
    cudaGetSymbolAddress((void**)&wqkv, g_wqkv);
    cudaGetSymbolAddress((void**)&wqks, g_wqks);

    float* out = (float*)d_out;                 // [B,T,C]
    float* sw  = out + (long long)ROWS_T * CC;  // spatial_weights [B,C,C]

    // pack weights
    cudaMemcpyAsync(wqkv,           Wq_t, 256 * 256 * 4, cudaMemcpyDeviceToDevice, 0);
    cudaMemcpyAsync(wqkv + 256*256, Wk_t, 256 * 256 * 4, cudaMemcpyDeviceToDevice, 0);
    cudaMemcpyAsync(wqkv + 512*256, Wv_t, 256 * 256 * 4, cudaMemcpyDeviceToDevice, 0);
    cudaMemcpyAsync(wqks,           Wq_s, 512 * 512 * 4, cudaMemcpyDeviceToDevice, 0);
    cudaMemcpyAsync(wqks + 512*512, Wk_s, 512 * 512 * 4, cudaMemcpyDeviceToDevice, 0);

    // ---- temporal branch ----
    ln_kernel<<<ROWS_T, 256>>>(x_T, t_ln1_w, t_ln1_b, h, CC);
    gemm(h, wqkv, 0, 0, qkv, ROWS_T, 768, CC, CC, CC, 768, 1,1, 0,0,0,0,0,0, 0);
    attn_tc<<<dim3(TT/64, BB*HH), 128>>>(qkv, o);
    gemm(o, Wo, 0, x_T, x, ROWS_T, CC, CC, CC, CC, CC, 1,1, 0,0,0,0,0,0, 0);
    ln_kernel<<<ROWS_T, 256>>>(x, t_ln2_w, t_ln2_b, h, CC);
    gemm(h, ff1_w1, ff1_b1, 0, u,  ROWS_T, 4*CC, CC, CC, CC, 4*CC, 1,1, 0,0,0,0,0,0, 1);
    gemm(u, ff1_w2, ff1_b2, x, to, ROWS_T, CC, 4*CC, 4*CC, 4*CC, CC, 1,1, 0,0,0,0,0,0, 0);

    // ---- spatial branch ----
    ln_kernel<<<ROWS_S, 256>>>(x_S, s_ln1_w, s_ln1_b, hs, TT);
    gemm(hs, wqks, 0, 0, qks, ROWS_S, 1024, TT, TT, TT, 1024, 1,1, 0,0,0,0,0,0, 0);
    gemm(qks, qks + 512, 0, 0, sc, CC, CC, HS_S, 1024, 1024, CC,
         BB*HH, HH,
         (long long)CC*1024, 64, (long long)CC*1024, 64,
         (long long)HH*CC*CC, (long long)CC*CC, 0);
    smax_mean_kernel<<<BB*CC, 256>>>(sc, sw);

    // ---- fusion: x2 = TO + TO @ sw^T (batched over b) ----
    gemm(to, sw, 0, to, x2, TT, CC, CC, CC, CC, CC,
         BB, 1,
         (long long)TT*CC, 0, (long long)CC*CC, 0, (long long)TT*CC, 0, 0);

    // ---- FFN2 -> out ----
    ln_kernel<<<ROWS_T, 256>>>(x2, fus_ln_w, fus_ln_b, h, CC);
    gemm(h, ff2_w1, ff2_b1, 0, u, ROWS_T, 4*CC, CC, CC, CC, 4*CC, 1,1, 0,0,0,0,0,0, 1);
    gemm(u, ff2_w2, ff2_b2, x2, out, ROWS_T, CC, 4*CC, 4*CC, 4*CC, CC, 1,1, 0,0,0,0,0,0, 0);
}